// round 1
// baseline (speedup 1.0000x reference)
#include <cuda_runtime.h>
#include <cuda_bf16.h>
#include <math.h>

#define NUM_LAYERS 2
#define B_SZ 2
#define S_TOTAL 13294
#define D_MODEL 256
#define NH 8
#define DH 32
#define NL 4
#define NP 4
#define DFF 1024
#define M_TOTAL (B_SZ * S_TOTAL)

__constant__ int c_H[4]     = {100, 50, 25, 13};
__constant__ int c_W[4]     = {100, 50, 25, 13};
__constant__ int c_start[4] = {0, 10000, 12500, 13125};

// ---------------- scratch (static device globals; no allocation) -------------
__device__ float g_value[M_TOTAL * D_MODEL];
__device__ float g_off  [M_TOTAL * D_MODEL];
__device__ float g_attn [M_TOTAL * 128];
__device__ float g_msda [M_TOTAL * D_MODEL];
__device__ float g_tmp  [M_TOTAL * D_MODEL];
__device__ float g_x    [M_TOTAL * D_MODEL];
__device__ float g_hid  [M_TOTAL * DFF];
__device__ float g_ref  [M_TOTAL * NL * 2];

// ---------------- reference points ------------------------------------------
__global__ void ref_kernel(const float* __restrict__ vr, float* __restrict__ ref)
{
    int idx = blockIdx.x * blockDim.x + threadIdx.x;
    if (idx >= B_SZ * S_TOTAL) return;
    int b = idx / S_TOTAL;
    int s = idx % S_TOTAL;

    int lvl = 0, rem = s;
    while (lvl < 3 && rem >= c_H[lvl] * c_W[lvl]) { rem -= c_H[lvl] * c_W[lvl]; lvl++; }
    int W_ = c_W[lvl], H_ = c_H[lvl];
    int i = rem / W_, j = rem % W_;

    float vrx = vr[(b * NL + lvl) * 2 + 0];
    float vry = vr[(b * NL + lvl) * 2 + 1];
    float bx = (j + 0.5f) / (vrx * (float)W_);
    float by = (i + 0.5f) / (vry * (float)H_);

    #pragma unroll
    for (int l = 0; l < NL; l++) {
        float vx = vr[(b * NL + l) * 2 + 0];
        float vy = vr[(b * NL + l) * 2 + 1];
        ref[((size_t)idx * NL + l) * 2 + 0] = bx * vx;
        ref[((size_t)idx * NL + l) * 2 + 1] = by * vy;
    }
}

// ---------------- tiled fp32 GEMM:  C[M,N] = A[M,K] @ W[K,N] + bias ----------
// BM=BN=128, BK=8, 256 threads, 8x8 per-thread microtile
__global__ void gemm_bias_kernel(const float* __restrict__ A,
                                 const float* __restrict__ W,
                                 const float* __restrict__ bias,
                                 float* __restrict__ C,
                                 int M, int N, int K, int doRelu)
{
    __shared__ float As[8][128];
    __shared__ float Bs[8][132];   // +4 pad

    const int bm = blockIdx.y * 128;
    const int bn = blockIdx.x * 128;
    const int tid = threadIdx.x;
    const int tr = tid >> 4;        // 0..15
    const int tc = tid & 15;        // 0..15

    const int arow = tid >> 1;          // 0..127
    const int acol = (tid & 1) * 4;     // 0 or 4
    const int brow = tid >> 5;          // 0..7
    const int bcol = (tid & 31) * 4;    // 0..124

    float acc[8][8];
    #pragma unroll
    for (int i = 0; i < 8; i++)
        #pragma unroll
        for (int j = 0; j < 8; j++) acc[i][j] = 0.f;

    for (int k0 = 0; k0 < K; k0 += 8) {
        float4 av = make_float4(0.f, 0.f, 0.f, 0.f);
        if (bm + arow < M)
            av = *(const float4*)(A + (size_t)(bm + arow) * K + k0 + acol);
        As[acol + 0][arow] = av.x;
        As[acol + 1][arow] = av.y;
        As[acol + 2][arow] = av.z;
        As[acol + 3][arow] = av.w;

        float4 bv = *(const float4*)(W + (size_t)(k0 + brow) * N + bn + bcol);
        *(float4*)&Bs[brow][bcol] = bv;
        __syncthreads();

        #pragma unroll
        for (int kk = 0; kk < 8; kk++) {
            float a[8], bb[8];
            #pragma unroll
            for (int i = 0; i < 8; i++) a[i] = As[kk][tr * 8 + i];
            #pragma unroll
            for (int j = 0; j < 8; j++) bb[j] = Bs[kk][tc * 8 + j];
            #pragma unroll
            for (int i = 0; i < 8; i++)
                #pragma unroll
                for (int j = 0; j < 8; j++)
                    acc[i][j] = fmaf(a[i], bb[j], acc[i][j]);
        }
        __syncthreads();
    }

    #pragma unroll
    for (int i = 0; i < 8; i++) {
        int row = bm + tr * 8 + i;
        if (row >= M) continue;
        #pragma unroll
        for (int j = 0; j < 8; j++) {
            float c = acc[i][j] + bias[bn + tc * 8 + j];
            if (doRelu) c = fmaxf(c, 0.f);
            C[(size_t)row * N + bn + tc * 8 + j] = c;
        }
    }
}

// ---------------- MSDA: one warp per (b, q, head); lane = channel ------------
__global__ void msda_kernel(const float* __restrict__ value,
                            const float* __restrict__ off,
                            const float* __restrict__ attn_logits,
                            const float* __restrict__ ref,
                            float* __restrict__ out)
{
    int gwarp = (blockIdx.x * blockDim.x + threadIdx.x) >> 5;
    int lane  = threadIdx.x & 31;
    if (gwarp >= B_SZ * S_TOTAL * NH) return;

    int h  = gwarp % NH;
    int bq = gwarp / NH;           // b*S + q
    int b  = bq / S_TOTAL;

    // softmax over 16 sampling logits (lanes 0..15 hold them)
    const float* lg = attn_logits + (size_t)bq * 128 + h * 16;
    float v = (lane < 16) ? lg[lane] : -1e30f;
    float m = v;
    #pragma unroll
    for (int o = 16; o > 0; o >>= 1) m = fmaxf(m, __shfl_xor_sync(0xffffffffu, m, o));
    float e = (lane < 16) ? __expf(v - m) : 0.f;
    float ssum = e;
    #pragma unroll
    for (int o = 16; o > 0; o >>= 1) ssum += __shfl_xor_sync(0xffffffffu, ssum, o);
    float aw = e / ssum;   // lane's attention weight for sample index == lane

    const float* offp = off + (size_t)bq * 256 + h * 32;   // [NL,NP,2]

    float acc = 0.f;
    #pragma unroll
    for (int l = 0; l < NL; l++) {
        float refx = ref[((size_t)bq * NL + l) * 2 + 0];
        float refy = ref[((size_t)bq * NL + l) * 2 + 1];
        int H_ = c_H[l], W_ = c_W[l], st = c_start[l];
        const float* vbase = value + ((size_t)(b * S_TOTAL + st) * NH + h) * DH + lane;
        float invW = 1.f / (float)W_, invH = 1.f / (float)H_;

        #pragma unroll
        for (int p = 0; p < NP; p++) {
            int idx16 = l * NP + p;
            float w16 = __shfl_sync(0xffffffffu, aw, idx16);
            float ox = offp[idx16 * 2 + 0];
            float oy = offp[idx16 * 2 + 1];
            float x = (refx + ox * invW) * (float)W_ - 0.5f;
            float y = (refy + oy * invH) * (float)H_ - 0.5f;
            float x0f = floorf(x), y0f = floorf(y);
            int x0 = (int)x0f, y0 = (int)y0f;
            float fx = x - x0f, fy = y - y0f;
            float w00 = (1.f - fx) * (1.f - fy);
            float w10 = fx * (1.f - fy);
            float w01 = (1.f - fx) * fy;
            float w11 = fx * fy;

            float s = 0.f;
            bool xin0 = (x0 >= 0) & (x0 < W_);
            bool xin1 = (x0 + 1 >= 0) & (x0 + 1 < W_);
            bool yin0 = (y0 >= 0) & (y0 < H_);
            bool yin1 = (y0 + 1 >= 0) & (y0 + 1 < H_);
            if (xin0 & yin0) s += w00 * vbase[(size_t)(y0 * W_ + x0) * (NH * DH)];
            if (xin1 & yin0) s += w10 * vbase[(size_t)(y0 * W_ + x0 + 1) * (NH * DH)];
            if (xin0 & yin1) s += w01 * vbase[(size_t)((y0 + 1) * W_ + x0) * (NH * DH)];
            if (xin1 & yin1) s += w11 * vbase[(size_t)((y0 + 1) * W_ + x0 + 1) * (NH * DH)];
            acc += w16 * s;
        }
    }
    out[((size_t)bq * NH + h) * DH + lane] = acc;
}

// ---------------- residual add + LayerNorm (one block per row, 256 thr) -----
__global__ void add_ln_kernel(const float* __restrict__ xin,
                              const float* __restrict__ r,
                              const float* __restrict__ g,
                              const float* __restrict__ bt,
                              float* __restrict__ xout)
{
    int row = blockIdx.x;
    int t = threadIdx.x;
    float v = xin[(size_t)row * 256 + t] + r[(size_t)row * 256 + t];

    float s1 = v, s2 = v * v;
    #pragma unroll
    for (int o = 16; o > 0; o >>= 1) {
        s1 += __shfl_xor_sync(0xffffffffu, s1, o);
        s2 += __shfl_xor_sync(0xffffffffu, s2, o);
    }
    __shared__ float sh1[8], sh2[8];
    int w = t >> 5, lane = t & 31;
    if (lane == 0) { sh1[w] = s1; sh2[w] = s2; }
    __syncthreads();
    if (w == 0) {
        s1 = (lane < 8) ? sh1[lane] : 0.f;
        s2 = (lane < 8) ? sh2[lane] : 0.f;
        #pragma unroll
        for (int o = 4; o > 0; o >>= 1) {
            s1 += __shfl_xor_sync(0xffffffffu, s1, o);
            s2 += __shfl_xor_sync(0xffffffffu, s2, o);
        }
        if (lane == 0) { sh1[0] = s1; sh2[0] = s2; }
    }
    __syncthreads();
    float mean = sh1[0] * (1.f / 256.f);
    float var  = sh2[0] * (1.f / 256.f) - mean * mean;
    float inv  = rsqrtf(var + 1e-5f);
    xout[(size_t)row * 256 + t] = (v - mean) * inv * g[t] + bt[t];
}

// -----------------------------------------------------------------------------
extern "C" void kernel_launch(void* const* d_in, const int* in_sizes, int n_in,
                              void* d_out, int out_size)
{
    const float* src    = (const float*)d_in[0];
    // d_in[1]: spatial_shapes (int64) — compile-time constants, unused
    const float* vr     = (const float*)d_in[2];
    const float* W_off  = (const float*)d_in[3];
    const float* b_off  = (const float*)d_in[4];
    const float* W_attn = (const float*)d_in[5];
    const float* b_attn = (const float*)d_in[6];
    const float* W_val  = (const float*)d_in[7];
    const float* b_val  = (const float*)d_in[8];
    const float* W_out  = (const float*)d_in[9];
    const float* b_out  = (const float*)d_in[10];
    const float* ln1_g  = (const float*)d_in[11];
    const float* ln1_b  = (const float*)d_in[12];
    const float* W1     = (const float*)d_in[13];
    const float* b1     = (const float*)d_in[14];
    const float* W2     = (const float*)d_in[15];
    const float* b2     = (const float*)d_in[16];
    const float* ln2_g  = (const float*)d_in[17];
    const float* ln2_b  = (const float*)d_in[18];

    float *value, *off, *attn, *msda, *tmp, *xb, *hid, *refp;
    cudaGetSymbolAddress((void**)&value, g_value);
    cudaGetSymbolAddress((void**)&off,   g_off);
    cudaGetSymbolAddress((void**)&attn,  g_attn);
    cudaGetSymbolAddress((void**)&msda,  g_msda);
    cudaGetSymbolAddress((void**)&tmp,   g_tmp);
    cudaGetSymbolAddress((void**)&xb,    g_x);
    cudaGetSymbolAddress((void**)&hid,   g_hid);
    cudaGetSymbolAddress((void**)&refp,  g_ref);

    const int M = M_TOTAL;
    const int GM = (M + 127) / 128;   // 208

    ref_kernel<<<(M + 255) / 256, 256>>>(vr, refp);

    for (int i = 0; i < NUM_LAYERS; i++) {
        const float* xin = (i == 0) ? src : xb;

        gemm_bias_kernel<<<dim3(2, GM), 256>>>(xin, W_val + (size_t)i * 256 * 256,
                                               b_val + i * 256, value, M, 256, 256, 0);
        gemm_bias_kernel<<<dim3(2, GM), 256>>>(xin, W_off + (size_t)i * 256 * 256,
                                               b_off + i * 256, off, M, 256, 256, 0);
        gemm_bias_kernel<<<dim3(1, GM), 256>>>(xin, W_attn + (size_t)i * 256 * 128,
                                               b_attn + i * 128, attn, M, 128, 256, 0);

        int nwarps = B_SZ * S_TOTAL * NH;
        msda_kernel<<<(nwarps * 32 + 255) / 256, 256>>>(value, off, attn, refp, msda);

        gemm_bias_kernel<<<dim3(2, GM), 256>>>(msda, W_out + (size_t)i * 256 * 256,
                                               b_out + i * 256, tmp, M, 256, 256, 0);
        add_ln_kernel<<<M, 256>>>(xin, tmp, ln1_g + i * 256, ln1_b + i * 256, xb);

        gemm_bias_kernel<<<dim3(8, GM), 256>>>(xb, W1 + (size_t)i * 256 * 1024,
                                               b1 + i * 1024, hid, M, 1024, 256, 1);
        gemm_bias_kernel<<<dim3(2, GM), 256>>>(hid, W2 + (size_t)i * 1024 * 256,
                                               b2 + i * 256, tmp, M, 256, 1024, 0);

        float* lnout = (i == NUM_LAYERS - 1) ? (float*)d_out : xb;
        add_ln_kernel<<<M, 256>>>(xb, tmp, ln2_g + i * 256, ln2_b + i * 256, lnout);
    }
}

// round 2
// speedup vs baseline: 1.0021x; 1.0021x over previous
#include <cuda_runtime.h>
#include <cuda_bf16.h>
#include <math.h>

#define NUM_LAYERS 2
#define B_SZ 2
#define S_TOTAL 13294
#define D_MODEL 256
#define NH 8
#define DH 32
#define NL 4
#define NP 4
#define DFF 1024
#define M_TOTAL (B_SZ * S_TOTAL)

__constant__ int c_H[4]     = {100, 50, 25, 13};
__constant__ int c_W[4]     = {100, 50, 25, 13};
__constant__ int c_start[4] = {0, 10000, 12500, 13125};

// ---------------- scratch (static device globals; no allocation) -------------
__device__ float g_value[M_TOTAL * D_MODEL];
__device__ float g_off  [M_TOTAL * D_MODEL];
__device__ float g_attn [M_TOTAL * 128];
__device__ float g_msda [M_TOTAL * D_MODEL];
__device__ float g_tmp  [M_TOTAL * D_MODEL];
__device__ float g_x    [M_TOTAL * D_MODEL];
__device__ float g_hid  [M_TOTAL * DFF];
__device__ float g_ref  [M_TOTAL * NL * 2];

// ---------------- reference points ------------------------------------------
__global__ void ref_kernel(const float* __restrict__ vr, float* __restrict__ ref)
{
    int idx = blockIdx.x * blockDim.x + threadIdx.x;
    if (idx >= B_SZ * S_TOTAL) return;
    int b = idx / S_TOTAL;
    int s = idx % S_TOTAL;

    int lvl = 0, rem = s;
    while (lvl < 3 && rem >= c_H[lvl] * c_W[lvl]) { rem -= c_H[lvl] * c_W[lvl]; lvl++; }
    int W_ = c_W[lvl], H_ = c_H[lvl];
    int i = rem / W_, j = rem % W_;

    float vrx = vr[(b * NL + lvl) * 2 + 0];
    float vry = vr[(b * NL + lvl) * 2 + 1];
    float bx = (j + 0.5f) / (vrx * (float)W_);
    float by = (i + 0.5f) / (vry * (float)H_);

    #pragma unroll
    for (int l = 0; l < NL; l++) {
        float vx = vr[(b * NL + l) * 2 + 0];
        float vy = vr[(b * NL + l) * 2 + 1];
        ref[((size_t)idx * NL + l) * 2 + 0] = bx * vx;
        ref[((size_t)idx * NL + l) * 2 + 1] = by * vy;
    }
}

// ---------------- packed-f32x2 tiled GEMM ------------------------------------
// C[M,N] = A[M,K] @ W[K,N] + bias  (optional relu)
// BM=BN=128, BK=16, 256 threads, 8x8 per-thread microtile computed as
// 8 rows x 4 packed col-pairs with fma.rn.f32x2 (FFMA2).
typedef unsigned long long u64;

#define FMA_F32X2(d, a, b, c) \
    asm("fma.rn.f32x2 %0, %1, %2, %3;" : "=l"(d) : "l"(a), "l"(b), "l"(c))

__global__ __launch_bounds__(256)
void gemm_bias_kernel(const float* __restrict__ A,
                      const float* __restrict__ W,
                      const float* __restrict__ bias,
                      float* __restrict__ C,
                      int M, int N, int K, int doRelu)
{
    // A values duplicated (v,v) so the inner loop reads packed operands directly
    __shared__ float As[2][16][256];   // [buf][k][2*m] 16 KB each
    __shared__ float Bs[2][16][128];   // [buf][k][n]    8 KB each

    const int bm = blockIdx.y * 128;
    const int bn = blockIdx.x * 128;
    const int tid = threadIdx.x;
    const int tr = tid >> 4;        // 0..15
    const int tc = tid & 15;        // 0..15

    // A tile loader mapping: 128 rows x 16 cols, 2 threads/row, 8 cols each
    const int arow = tid >> 1;
    const int acol = (tid & 1) * 8;
    // B tile loader mapping: 16 rows x 128 cols = 512 float4, 2 per thread
    const int br0 = tid >> 5;            // idx = tid       -> row 0..7
    const int bc0 = (tid & 31) * 4;
    const int br1 = 8 + (tid >> 5);      // idx = tid + 256 -> row 8..15
    const int bc1 = bc0;

    u64 acc[8][4];
    #pragma unroll
    for (int i = 0; i < 8; i++)
        #pragma unroll
        for (int j = 0; j < 4; j++) acc[i][j] = 0ull;

    const int NT = K >> 4;

    float4 pa0, pa1, pb0, pb1;

    // prologue: load tile 0
    {
        pa0 = make_float4(0.f, 0.f, 0.f, 0.f);
        pa1 = pa0;
        if (bm + arow < M) {
            const float* ap = A + (size_t)(bm + arow) * K + acol;
            pa0 = *(const float4*)(ap);
            pa1 = *(const float4*)(ap + 4);
        }
        pb0 = *(const float4*)(W + (size_t)br0 * N + bn + bc0);
        pb1 = *(const float4*)(W + (size_t)br1 * N + bn + bc1);

        As[0][acol + 0][2 * arow] = pa0.x; As[0][acol + 0][2 * arow + 1] = pa0.x;
        As[0][acol + 1][2 * arow] = pa0.y; As[0][acol + 1][2 * arow + 1] = pa0.y;
        As[0][acol + 2][2 * arow] = pa0.z; As[0][acol + 2][2 * arow + 1] = pa0.z;
        As[0][acol + 3][2 * arow] = pa0.w; As[0][acol + 3][2 * arow + 1] = pa0.w;
        As[0][acol + 4][2 * arow] = pa1.x; As[0][acol + 4][2 * arow + 1] = pa1.x;
        As[0][acol + 5][2 * arow] = pa1.y; As[0][acol + 5][2 * arow + 1] = pa1.y;
        As[0][acol + 6][2 * arow] = pa1.z; As[0][acol + 6][2 * arow + 1] = pa1.z;
        As[0][acol + 7][2 * arow] = pa1.w; As[0][acol + 7][2 * arow + 1] = pa1.w;
        *(float4*)&Bs[0][br0][bc0] = pb0;
        *(float4*)&Bs[0][br1][bc1] = pb1;
    }
    __syncthreads();

    for (int t = 0; t < NT; t++) {
        const int cur = t & 1;
        const int nxt = cur ^ 1;

        // prefetch next tile into registers
        if (t + 1 < NT) {
            const int k0 = (t + 1) << 4;
            pa0 = make_float4(0.f, 0.f, 0.f, 0.f);
            pa1 = pa0;
            if (bm + arow < M) {
                const float* ap = A + (size_t)(bm + arow) * K + k0 + acol;
                pa0 = *(const float4*)(ap);
                pa1 = *(const float4*)(ap + 4);
            }
            pb0 = *(const float4*)(W + (size_t)(k0 + br0) * N + bn + bc0);
            pb1 = *(const float4*)(W + (size_t)(k0 + br1) * N + bn + bc1);
        }

        // compute on current buffer
        #pragma unroll
        for (int kk = 0; kk < 16; kk++) {
            const float* arp = &As[cur][kk][tr * 16];
            ulonglong2 A01 = *(const ulonglong2*)(arp);
            ulonglong2 A23 = *(const ulonglong2*)(arp + 4);
            ulonglong2 A45 = *(const ulonglong2*)(arp + 8);
            ulonglong2 A67 = *(const ulonglong2*)(arp + 12);
            ulonglong2 B03 = *(const ulonglong2*)&Bs[cur][kk][tc * 8];
            ulonglong2 B47 = *(const ulonglong2*)&Bs[cur][kk][tc * 8 + 4];

            u64 ad[8] = {A01.x, A01.y, A23.x, A23.y, A45.x, A45.y, A67.x, A67.y};
            u64 bp[4] = {B03.x, B03.y, B47.x, B47.y};

            #pragma unroll
            for (int i = 0; i < 8; i++) {
                FMA_F32X2(acc[i][0], ad[i], bp[0], acc[i][0]);
                FMA_F32X2(acc[i][1], ad[i], bp[1], acc[i][1]);
                FMA_F32X2(acc[i][2], ad[i], bp[2], acc[i][2]);
                FMA_F32X2(acc[i][3], ad[i], bp[3], acc[i][3]);
            }
        }

        // stage prefetched tile into the other buffer
        if (t + 1 < NT) {
            As[nxt][acol + 0][2 * arow] = pa0.x; As[nxt][acol + 0][2 * arow + 1] = pa0.x;
            As[nxt][acol + 1][2 * arow] = pa0.y; As[nxt][acol + 1][2 * arow + 1] = pa0.y;
            As[nxt][acol + 2][2 * arow] = pa0.z; As[nxt][acol + 2][2 * arow + 1] = pa0.z;
            As[nxt][acol + 3][2 * arow] = pa0.w; As[nxt][acol + 3][2 * arow + 1] = pa0.w;
            As[nxt][acol + 4][2 * arow] = pa1.x; As[nxt][acol + 4][2 * arow + 1] = pa1.x;
            As[nxt][acol + 5][2 * arow] = pa1.y; As[nxt][acol + 5][2 * arow + 1] = pa1.y;
            As[nxt][acol + 6][2 * arow] = pa1.z; As[nxt][acol + 6][2 * arow + 1] = pa1.z;
            As[nxt][acol + 7][2 * arow] = pa1.w; As[nxt][acol + 7][2 * arow + 1] = pa1.w;
            *(float4*)&Bs[nxt][br0][bc0] = pb0;
            *(float4*)&Bs[nxt][br1][bc1] = pb1;
        }
        __syncthreads();
    }

    // epilogue
    #pragma unroll
    for (int i = 0; i < 8; i++) {
        int row = bm + tr * 8 + i;
        if (row >= M) continue;
        float out[8];
        #pragma unroll
        for (int jp = 0; jp < 4; jp++) {
            u64 u = acc[i][jp];
            out[2 * jp + 0] = __uint_as_float((unsigned)(u & 0xffffffffu));
            out[2 * jp + 1] = __uint_as_float((unsigned)(u >> 32));
        }
        #pragma unroll
        for (int j = 0; j < 8; j++) {
            float c = out[j] + bias[bn + tc * 8 + j];
            if (doRelu) c = fmaxf(c, 0.f);
            out[j] = c;
        }
        *(float4*)(C + (size_t)row * N + bn + tc * 8)     = make_float4(out[0], out[1], out[2], out[3]);
        *(float4*)(C + (size_t)row * N + bn + tc * 8 + 4) = make_float4(out[4], out[5], out[6], out[7]);
    }
}

// ---------------- MSDA: one warp per (b, q, head); lane = channel ------------
__global__ void msda_kernel(const float* __restrict__ value,
                            const float* __restrict__ off,
                            const float* __restrict__ attn_logits,
                            const float* __restrict__ ref,
                            float* __restrict__ out)
{
    int gwarp = (blockIdx.x * blockDim.x + threadIdx.x) >> 5;
    int lane  = threadIdx.x & 31;
    if (gwarp >= B_SZ * S_TOTAL * NH) return;

    int h  = gwarp % NH;
    int bq = gwarp / NH;           // b*S + q
    int b  = bq / S_TOTAL;

    // softmax over 16 sampling logits (lanes 0..15 hold them)
    const float* lg = attn_logits + (size_t)bq * 128 + h * 16;
    float v = (lane < 16) ? lg[lane] : -1e30f;
    float m = v;
    #pragma unroll
    for (int o = 16; o > 0; o >>= 1) m = fmaxf(m, __shfl_xor_sync(0xffffffffu, m, o));
    float e = (lane < 16) ? __expf(v - m) : 0.f;
    float ssum = e;
    #pragma unroll
    for (int o = 16; o > 0; o >>= 1) ssum += __shfl_xor_sync(0xffffffffu, ssum, o);
    float aw = e / ssum;   // lane's attention weight for sample index == lane

    const float* offp = off + (size_t)bq * 256 + h * 32;   // [NL,NP,2]

    float acc = 0.f;
    #pragma unroll
    for (int l = 0; l < NL; l++) {
        float refx = ref[((size_t)bq * NL + l) * 2 + 0];
        float refy = ref[((size_t)bq * NL + l) * 2 + 1];
        int H_ = c_H[l], W_ = c_W[l], st = c_start[l];
        const float* vbase = value + ((size_t)(b * S_TOTAL + st) * NH + h) * DH + lane;
        float invW = 1.f / (float)W_, invH = 1.f / (float)H_;

        #pragma unroll
        for (int p = 0; p < NP; p++) {
            int idx16 = l * NP + p;
            float w16 = __shfl_sync(0xffffffffu, aw, idx16);
            float ox = offp[idx16 * 2 + 0];
            float oy = offp[idx16 * 2 + 1];
            float x = (refx + ox * invW) * (float)W_ - 0.5f;
            float y = (refy + oy * invH) * (float)H_ - 0.5f;
            float x0f = floorf(x), y0f = floorf(y);
            int x0 = (int)x0f, y0 = (int)y0f;
            float fx = x - x0f, fy = y - y0f;
            float w00 = (1.f - fx) * (1.f - fy);
            float w10 = fx * (1.f - fy);
            float w01 = (1.f - fx) * fy;
            float w11 = fx * fy;

            float s = 0.f;
            bool xin0 = (x0 >= 0) & (x0 < W_);
            bool xin1 = (x0 + 1 >= 0) & (x0 + 1 < W_);
            bool yin0 = (y0 >= 0) & (y0 < H_);
            bool yin1 = (y0 + 1 >= 0) & (y0 + 1 < H_);
            if (xin0 & yin0) s += w00 * vbase[(size_t)(y0 * W_ + x0) * (NH * DH)];
            if (xin1 & yin0) s += w10 * vbase[(size_t)(y0 * W_ + x0 + 1) * (NH * DH)];
            if (xin0 & yin1) s += w01 * vbase[(size_t)((y0 + 1) * W_ + x0) * (NH * DH)];
            if (xin1 & yin1) s += w11 * vbase[(size_t)((y0 + 1) * W_ + x0 + 1) * (NH * DH)];
            acc += w16 * s;
        }
    }
    out[((size_t)bq * NH + h) * DH + lane] = acc;
}

// ---------------- residual add + LayerNorm (one block per row, 256 thr) -----
__global__ void add_ln_kernel(const float* __restrict__ xin,
                              const float* __restrict__ r,
                              const float* __restrict__ g,
                              const float* __restrict__ bt,
                              float* __restrict__ xout)
{
    int row = blockIdx.x;
    int t = threadIdx.x;
    float v = xin[(size_t)row * 256 + t] + r[(size_t)row * 256 + t];

    float s1 = v, s2 = v * v;
    #pragma unroll
    for (int o = 16; o > 0; o >>= 1) {
        s1 += __shfl_xor_sync(0xffffffffu, s1, o);
        s2 += __shfl_xor_sync(0xffffffffu, s2, o);
    }
    __shared__ float sh1[8], sh2[8];
    int w = t >> 5, lane = t & 31;
    if (lane == 0) { sh1[w] = s1; sh2[w] = s2; }
    __syncthreads();
    if (w == 0) {
        s1 = (lane < 8) ? sh1[lane] : 0.f;
        s2 = (lane < 8) ? sh2[lane] : 0.f;
        #pragma unroll
        for (int o = 4; o > 0; o >>= 1) {
            s1 += __shfl_xor_sync(0xffffffffu, s1, o);
            s2 += __shfl_xor_sync(0xffffffffu, s2, o);
        }
        if (lane == 0) { sh1[0] = s1; sh2[0] = s2; }
    }
    __syncthreads();
    float mean = sh1[0] * (1.f / 256.f);
    float var  = sh2[0] * (1.f / 256.f) - mean * mean;
    float inv  = rsqrtf(var + 1e-5f);
    xout[(size_t)row * 256 + t] = (v - mean) * inv * g[t] + bt[t];
}

// -----------------------------------------------------------------------------
extern "C" void kernel_launch(void* const* d_in, const int* in_sizes, int n_in,
                              void* d_out, int out_size)
{
    const float* src    = (const float*)d_in[0];
    // d_in[1]: spatial_shapes (int64) — compile-time constants, unused
    const float* vr     = (const float*)d_in[2];
    const float* W_off  = (const float*)d_in[3];
    const float* b_off  = (const float*)d_in[4];
    const float* W_attn = (const float*)d_in[5];
    const float* b_attn = (const float*)d_in[6];
    const float* W_val  = (const float*)d_in[7];
    const float* b_val  = (const float*)d_in[8];
    const float* W_out  = (const float*)d_in[9];
    const float* b_out  = (const float*)d_in[10];
    const float* ln1_g  = (const float*)d_in[11];
    const float* ln1_b  = (const float*)d_in[12];
    const float* W1     = (const float*)d_in[13];
    const float* b1     = (const float*)d_in[14];
    const float* W2     = (const float*)d_in[15];
    const float* b2     = (const float*)d_in[16];
    const float* ln2_g  = (const float*)d_in[17];
    const float* ln2_b  = (const float*)d_in[18];

    float *value, *off, *attn, *msda, *tmp, *xb, *hid, *refp;
    cudaGetSymbolAddress((void**)&value, g_value);
    cudaGetSymbolAddress((void**)&off,   g_off);
    cudaGetSymbolAddress((void**)&attn,  g_attn);
    cudaGetSymbolAddress((void**)&msda,  g_msda);
    cudaGetSymbolAddress((void**)&tmp,   g_tmp);
    cudaGetSymbolAddress((void**)&xb,    g_x);
    cudaGetSymbolAddress((void**)&hid,   g_hid);
    cudaGetSymbolAddress((void**)&refp,  g_ref);

    const int M = M_TOTAL;
    const int GM = (M + 127) / 128;   // 208

    ref_kernel<<<(M + 255) / 256, 256>>>(vr, refp);

    for (int i = 0; i < NUM_LAYERS; i++) {
        const float* xin = (i == 0) ? src : xb;

        gemm_bias_kernel<<<dim3(2, GM), 256>>>(xin, W_val + (size_t)i * 256 * 256,
                                               b_val + i * 256, value, M, 256, 256, 0);
        gemm_bias_kernel<<<dim3(2, GM), 256>>>(xin, W_off + (size_t)i * 256 * 256,
                                               b_off + i * 256, off, M, 256, 256, 0);
        gemm_bias_kernel<<<dim3(1, GM), 256>>>(xin, W_attn + (size_t)i * 256 * 128,
                                               b_attn + i * 128, attn, M, 128, 256, 0);

        int nwarps = B_SZ * S_TOTAL * NH;
        msda_kernel<<<(nwarps * 32 + 255) / 256, 256>>>(value, off, attn, refp, msda);

        gemm_bias_kernel<<<dim3(2, GM), 256>>>(msda, W_out + (size_t)i * 256 * 256,
                                               b_out + i * 256, tmp, M, 256, 256, 0);
        add_ln_kernel<<<M, 256>>>(xin, tmp, ln1_g + i * 256, ln1_b + i * 256, xb);

        gemm_bias_kernel<<<dim3(8, GM), 256>>>(xb, W1 + (size_t)i * 256 * 1024,
                                               b1 + i * 1024, hid, M, 1024, 256, 1);
        gemm_bias_kernel<<<dim3(2, GM), 256>>>(hid, W2 + (size_t)i * 1024 * 256,
                                               b2 + i * 256, tmp, M, 256, 1024, 0);

        float* lnout = (i == NUM_LAYERS - 1) ? (float*)d_out : xb;
        add_ln_kernel<<<M, 256>>>(xb, tmp, ln2_g + i * 256, ln2_b + i * 256, lnout);
    }
}

// round 4
// speedup vs baseline: 2.1785x; 2.1738x over previous
#include <cuda_runtime.h>
#include <cuda_bf16.h>
#include <math.h>

#define NUM_LAYERS 2
#define B_SZ 2
#define S_TOTAL 13294
#define D_MODEL 256
#define NH 8
#define DH 32
#define NL 4
#define NP 4
#define DFF 1024
#define M_TOTAL (B_SZ * S_TOTAL)

__constant__ int c_H[4]     = {100, 50, 25, 13};
__constant__ int c_W[4]     = {100, 50, 25, 13};
__constant__ int c_start[4] = {0, 10000, 12500, 13125};

// ---------------- scratch (static device globals; no allocation) -------------
__device__ float g_value[M_TOTAL * D_MODEL];
__device__ float g_off  [M_TOTAL * D_MODEL];
__device__ float g_attn [M_TOTAL * 128];
__device__ float g_msda [M_TOTAL * D_MODEL];
__device__ float g_tmp  [M_TOTAL * D_MODEL];
__device__ float g_x    [M_TOTAL * D_MODEL];
__device__ float g_hid  [M_TOTAL * DFF];
__device__ float g_ref  [M_TOTAL * NL * 2];

// ---------------- reference points ------------------------------------------
__global__ void ref_kernel(const float* __restrict__ vr, float* __restrict__ ref)
{
    int idx = blockIdx.x * blockDim.x + threadIdx.x;
    if (idx >= B_SZ * S_TOTAL) return;
    int b = idx / S_TOTAL;
    int s = idx % S_TOTAL;

    int lvl = 0, rem = s;
    while (lvl < 3 && rem >= c_H[lvl] * c_W[lvl]) { rem -= c_H[lvl] * c_W[lvl]; lvl++; }
    int W_ = c_W[lvl], H_ = c_H[lvl];
    int i = rem / W_, j = rem % W_;

    float vrx = vr[(b * NL + lvl) * 2 + 0];
    float vry = vr[(b * NL + lvl) * 2 + 1];
    float bx = (j + 0.5f) / (vrx * (float)W_);
    float by = (i + 0.5f) / (vry * (float)H_);

    #pragma unroll
    for (int l = 0; l < NL; l++) {
        float vx = vr[(b * NL + l) * 2 + 0];
        float vy = vr[(b * NL + l) * 2 + 1];
        ref[((size_t)idx * NL + l) * 2 + 0] = bx * vx;
        ref[((size_t)idx * NL + l) * 2 + 1] = by * vy;
    }
}

// ---------------- TF32 tensor-core GEMM --------------------------------------
// C[M,N] = A[M,K] @ W[K,N] + bias (optional relu), via mma.sync.m16n8k8.tf32
// BM=BN=128, BK=16, 256 threads = 8 warps in 2(M)x4(N); warp tile 64x32.
// Smem: A as [k][m] stride 136, B as [k][n] stride 136 (conflict-free frag reads).

__device__ __forceinline__ unsigned f2tf32(float f) {
    unsigned u;
    asm("cvt.rna.tf32.f32 %0, %1;" : "=r"(u) : "f"(f));
    return u;
}

#define MMA_TF32(c0,c1,c2,c3, a0,a1,a2,a3, b0,b1) \
    asm volatile("mma.sync.aligned.m16n8k8.row.col.f32.tf32.tf32.f32 " \
        "{%0,%1,%2,%3},{%4,%5,%6,%7},{%8,%9},{%0,%1,%2,%3};" \
        : "+f"(c0), "+f"(c1), "+f"(c2), "+f"(c3) \
        : "r"(a0), "r"(a1), "r"(a2), "r"(a3), "r"(b0), "r"(b1))

#define LDK 136

__global__ __launch_bounds__(256)
void gemm_tc_kernel(const float* __restrict__ A,
                    const float* __restrict__ W,
                    const float* __restrict__ bias,
                    float* __restrict__ C,
                    int M, int N, int K, int doRelu)
{
    __shared__ unsigned As[2][16][LDK];   // [buf][k][m]
    __shared__ unsigned Bs[2][16][LDK];   // [buf][k][n]

    const int bm = blockIdx.y * 128;
    const int bn = blockIdx.x * 128;
    const int tid  = threadIdx.x;
    const int lane = tid & 31;
    const int warp = tid >> 5;
    const int wm = (warp >> 2) * 64;   // 0 / 64
    const int wn = (warp & 3) * 32;    // 0..96

    // loaders
    const int arow = tid >> 1;          // 0..127
    const int acol = (tid & 1) * 8;     // 0 / 8
    const int brow = tid >> 4;          // 0..15
    const int bcol = (tid & 15) * 8;    // 0..120

    const int grow = lane >> 2;   // 0..7
    const int gk   = lane & 3;    // 0..3

    float c[4][4][4];
    #pragma unroll
    for (int i = 0; i < 4; i++)
        #pragma unroll
        for (int j = 0; j < 4; j++)
            #pragma unroll
            for (int r = 0; r < 4; r++) c[i][j][r] = 0.f;

    const int NT = K >> 4;
    float4 pa0, pa1, pb0, pb1;
    const bool arow_ok = (bm + arow < M);

    // prologue: tile 0
    {
        pa0 = make_float4(0.f,0.f,0.f,0.f); pa1 = pa0;
        if (arow_ok) {
            const float* ap = A + (size_t)(bm + arow) * K + acol;
            pa0 = *(const float4*)ap;
            pa1 = *(const float4*)(ap + 4);
        }
        pb0 = *(const float4*)(W + (size_t)brow * N + bn + bcol);
        pb1 = *(const float4*)(W + (size_t)brow * N + bn + bcol + 4);

        As[0][acol+0][arow] = f2tf32(pa0.x); As[0][acol+1][arow] = f2tf32(pa0.y);
        As[0][acol+2][arow] = f2tf32(pa0.z); As[0][acol+3][arow] = f2tf32(pa0.w);
        As[0][acol+4][arow] = f2tf32(pa1.x); As[0][acol+5][arow] = f2tf32(pa1.y);
        As[0][acol+6][arow] = f2tf32(pa1.z); As[0][acol+7][arow] = f2tf32(pa1.w);
        uint4 u0 = make_uint4(f2tf32(pb0.x), f2tf32(pb0.y), f2tf32(pb0.z), f2tf32(pb0.w));
        uint4 u1 = make_uint4(f2tf32(pb1.x), f2tf32(pb1.y), f2tf32(pb1.z), f2tf32(pb1.w));
        *(uint4*)&Bs[0][brow][bcol]     = u0;
        *(uint4*)&Bs[0][brow][bcol + 4] = u1;
    }
    __syncthreads();

    for (int t = 0; t < NT; t++) {
        const int cur = t & 1;
        const int nxt = cur ^ 1;

        if (t + 1 < NT) {
            const int k0 = (t + 1) << 4;
            pa0 = make_float4(0.f,0.f,0.f,0.f); pa1 = pa0;
            if (arow_ok) {
                const float* ap = A + (size_t)(bm + arow) * K + k0 + acol;
                pa0 = *(const float4*)ap;
                pa1 = *(const float4*)(ap + 4);
            }
            pb0 = *(const float4*)(W + (size_t)(k0 + brow) * N + bn + bcol);
            pb1 = *(const float4*)(W + (size_t)(k0 + brow) * N + bn + bcol + 4);
        }

        #pragma unroll
        for (int ks = 0; ks < 2; ks++) {
            const int kb = ks * 8;
            unsigned af[4][4], bf[4][2];
            #pragma unroll
            for (int mt = 0; mt < 4; mt++) {
                int r = wm + mt * 16 + grow;
                af[mt][0] = As[cur][kb + gk    ][r];
                af[mt][1] = As[cur][kb + gk    ][r + 8];
                af[mt][2] = As[cur][kb + gk + 4][r];
                af[mt][3] = As[cur][kb + gk + 4][r + 8];
            }
            #pragma unroll
            for (int nt = 0; nt < 4; nt++) {
                int n = wn + nt * 8 + grow;
                bf[nt][0] = Bs[cur][kb + gk    ][n];
                bf[nt][1] = Bs[cur][kb + gk + 4][n];
            }
            #pragma unroll
            for (int mt = 0; mt < 4; mt++)
                #pragma unroll
                for (int nt = 0; nt < 4; nt++)
                    MMA_TF32(c[mt][nt][0], c[mt][nt][1], c[mt][nt][2], c[mt][nt][3],
                             af[mt][0], af[mt][1], af[mt][2], af[mt][3],
                             bf[nt][0], bf[nt][1]);
        }

        if (t + 1 < NT) {
            As[nxt][acol+0][arow] = f2tf32(pa0.x); As[nxt][acol+1][arow] = f2tf32(pa0.y);
            As[nxt][acol+2][arow] = f2tf32(pa0.z); As[nxt][acol+3][arow] = f2tf32(pa0.w);
            As[nxt][acol+4][arow] = f2tf32(pa1.x); As[nxt][acol+5][arow] = f2tf32(pa1.y);
            As[nxt][acol+6][arow] = f2tf32(pa1.z); As[nxt][acol+7][arow] = f2tf32(pa1.w);
            uint4 u0 = make_uint4(f2tf32(pb0.x), f2tf32(pb0.y), f2tf32(pb0.z), f2tf32(pb0.w));
            uint4 u1 = make_uint4(f2tf32(pb1.x), f2tf32(pb1.y), f2tf32(pb1.z), f2tf32(pb1.w));
            *(uint4*)&Bs[nxt][brow][bcol]     = u0;
            *(uint4*)&Bs[nxt][brow][bcol + 4] = u1;
        }
        __syncthreads();
    }

    // epilogue: c0,c1 -> (row, col..col+1); c2,c3 -> (row+8, ...)
    #pragma unroll
    for (int mt = 0; mt < 4; mt++) {
        int row0 = bm + wm + mt * 16 + grow;
        #pragma unroll
        for (int nt = 0; nt < 4; nt++) {
            int gn = bn + wn + nt * 8 + (lane & 3) * 2;
            float b0 = bias[gn], b1 = bias[gn + 1];
            if (row0 < M) {
                float v0 = c[mt][nt][0] + b0;
                float v1 = c[mt][nt][1] + b1;
                if (doRelu) { v0 = fmaxf(v0, 0.f); v1 = fmaxf(v1, 0.f); }
                *(float2*)(C + (size_t)row0 * N + gn) = make_float2(v0, v1);
            }
            if (row0 + 8 < M) {
                float v2 = c[mt][nt][2] + b0;
                float v3 = c[mt][nt][3] + b1;
                if (doRelu) { v2 = fmaxf(v2, 0.f); v3 = fmaxf(v3, 0.f); }
                *(float2*)(C + (size_t)(row0 + 8) * N + gn) = make_float2(v2, v3);
            }
        }
    }
}

// ---------------- MSDA: one warp per (b, q, head); lane = channel ------------
__global__ void msda_kernel(const float* __restrict__ value,
                            const float* __restrict__ off,
                            const float* __restrict__ attn_logits,
                            const float* __restrict__ ref,
                            float* __restrict__ out)
{
    int gwarp = (blockIdx.x * blockDim.x + threadIdx.x) >> 5;
    int lane  = threadIdx.x & 31;
    if (gwarp >= B_SZ * S_TOTAL * NH) return;

    int h  = gwarp % NH;
    int bq = gwarp / NH;           // b*S + q
    int b  = bq / S_TOTAL;

    const float* lg = attn_logits + (size_t)bq * 128 + h * 16;
    float v = (lane < 16) ? lg[lane] : -1e30f;
    float m = v;
    #pragma unroll
    for (int o = 16; o > 0; o >>= 1) m = fmaxf(m, __shfl_xor_sync(0xffffffffu, m, o));
    float e = (lane < 16) ? __expf(v - m) : 0.f;
    float ssum = e;
    #pragma unroll
    for (int o = 16; o > 0; o >>= 1) ssum += __shfl_xor_sync(0xffffffffu, ssum, o);
    float aw = e / ssum;

    const float* offp = off + (size_t)bq * 256 + h * 32;

    float acc = 0.f;
    #pragma unroll
    for (int l = 0; l < NL; l++) {
        float refx = ref[((size_t)bq * NL + l) * 2 + 0];
        float refy = ref[((size_t)bq * NL + l) * 2 + 1];
        int H_ = c_H[l], W_ = c_W[l], st = c_start[l];
        const float* vbase = value + ((size_t)(b * S_TOTAL + st) * NH + h) * DH + lane;
        float invW = 1.f / (float)W_, invH = 1.f / (float)H_;

        #pragma unroll
        for (int p = 0; p < NP; p++) {
            int idx16 = l * NP + p;
            float w16 = __shfl_sync(0xffffffffu, aw, idx16);
            float ox = offp[idx16 * 2 + 0];
            float oy = offp[idx16 * 2 + 1];
            float x = (refx + ox * invW) * (float)W_ - 0.5f;
            float y = (refy + oy * invH) * (float)H_ - 0.5f;
            float x0f = floorf(x), y0f = floorf(y);
            int x0 = (int)x0f, y0 = (int)y0f;
            float fx = x - x0f, fy = y - y0f;
            float w00 = (1.f - fx) * (1.f - fy);
            float w10 = fx * (1.f - fy);
            float w01 = (1.f - fx) * fy;
            float w11 = fx * fy;

            float s = 0.f;
            bool xin0 = (x0 >= 0) & (x0 < W_);
            bool xin1 = (x0 + 1 >= 0) & (x0 + 1 < W_);
            bool yin0 = (y0 >= 0) & (y0 < H_);
            bool yin1 = (y0 + 1 >= 0) & (y0 + 1 < H_);
            if (xin0 & yin0) s += w00 * vbase[(size_t)(y0 * W_ + x0) * (NH * DH)];
            if (xin1 & yin0) s += w10 * vbase[(size_t)(y0 * W_ + x0 + 1) * (NH * DH)];
            if (xin0 & yin1) s += w01 * vbase[(size_t)((y0 + 1) * W_ + x0) * (NH * DH)];
            if (xin1 & yin1) s += w11 * vbase[(size_t)((y0 + 1) * W_ + x0 + 1) * (NH * DH)];
            acc += w16 * s;
        }
    }
    out[((size_t)bq * NH + h) * DH + lane] = acc;
}

// ---------------- residual add + LayerNorm (one block per row, 256 thr) -----
__global__ void add_ln_kernel(const float* __restrict__ xin,
                              const float* __restrict__ r,
                              const float* __restrict__ g,
                              const float* __restrict__ bt,
                              float* __restrict__ xout)
{
    int row = blockIdx.x;
    int t = threadIdx.x;
    float v = xin[(size_t)row * 256 + t] + r[(size_t)row * 256 + t];

    float s1 = v, s2 = v * v;
    #pragma unroll
    for (int o = 16; o > 0; o >>= 1) {
        s1 += __shfl_xor_sync(0xffffffffu, s1, o);
        s2 += __shfl_xor_sync(0xffffffffu, s2, o);
    }
    __shared__ float sh1[8], sh2[8];
    int w = t >> 5, lane = t & 31;
    if (lane == 0) { sh1[w] = s1; sh2[w] = s2; }
    __syncthreads();
    if (w == 0) {
        s1 = (lane < 8) ? sh1[lane] : 0.f;
        s2 = (lane < 8) ? sh2[lane] : 0.f;
        #pragma unroll
        for (int o = 4; o > 0; o >>= 1) {
            s1 += __shfl_xor_sync(0xffffffffu, s1, o);
            s2 += __shfl_xor_sync(0xffffffffu, s2, o);
        }
        if (lane == 0) { sh1[0] = s1; sh2[0] = s2; }
    }
    __syncthreads();
    float mean = sh1[0] * (1.f / 256.f);
    float var  = sh2[0] * (1.f / 256.f) - mean * mean;
    float inv  = rsqrtf(var + 1e-5f);
    xout[(size_t)row * 256 + t] = (v - mean) * inv * g[t] + bt[t];
}

// -----------------------------------------------------------------------------
extern "C" void kernel_launch(void* const* d_in, const int* in_sizes, int n_in,
                              void* d_out, int out_size)
{
    const float* src    = (const float*)d_in[0];
    const float* vr     = (const float*)d_in[2];
    const float* W_off  = (const float*)d_in[3];
    const float* b_off  = (const float*)d_in[4];
    const float* W_attn = (const float*)d_in[5];
    const float* b_attn = (const float*)d_in[6];
    const float* W_val  = (const float*)d_in[7];
    const float* b_val  = (const float*)d_in[8];
    const float* W_out  = (const float*)d_in[9];
    const float* b_out  = (const float*)d_in[10];
    const float* ln1_g  = (const float*)d_in[11];
    const float* ln1_b  = (const float*)d_in[12];
    const float* W1     = (const float*)d_in[13];
    const float* b1     = (const float*)d_in[14];
    const float* W2     = (const float*)d_in[15];
    const float* b2     = (const float*)d_in[16];
    const float* ln2_g  = (const float*)d_in[17];
    const float* ln2_b  = (const float*)d_in[18];

    float *value, *off, *attn, *msda, *tmp, *xb, *hid, *refp;
    cudaGetSymbolAddress((void**)&value, g_value);
    cudaGetSymbolAddress((void**)&off,   g_off);
    cudaGetSymbolAddress((void**)&attn,  g_attn);
    cudaGetSymbolAddress((void**)&msda,  g_msda);
    cudaGetSymbolAddress((void**)&tmp,   g_tmp);
    cudaGetSymbolAddress((void**)&xb,    g_x);
    cudaGetSymbolAddress((void**)&hid,   g_hid);
    cudaGetSymbolAddress((void**)&refp,  g_ref);

    const int M = M_TOTAL;
    const int GM = (M + 127) / 128;   // 208

    ref_kernel<<<(M + 255) / 256, 256>>>(vr, refp);

    for (int i = 0; i < NUM_LAYERS; i++) {
        const float* xin = (i == 0) ? src : xb;

        gemm_tc_kernel<<<dim3(2, GM), 256>>>(xin, W_val + (size_t)i * 256 * 256,
                                             b_val + i * 256, value, M, 256, 256, 0);
        gemm_tc_kernel<<<dim3(2, GM), 256>>>(xin, W_off + (size_t)i * 256 * 256,
                                             b_off + i * 256, off, M, 256, 256, 0);
        gemm_tc_kernel<<<dim3(1, GM), 256>>>(xin, W_attn + (size_t)i * 256 * 128,
                                             b_attn + i * 128, attn, M, 128, 256, 0);

        int nwarps = B_SZ * S_TOTAL * NH;
        msda_kernel<<<(nwarps * 32 + 255) / 256, 256>>>(value, off, attn, refp, msda);

        gemm_tc_kernel<<<dim3(2, GM), 256>>>(msda, W_out + (size_t)i * 256 * 256,
                                             b_out + i * 256, tmp, M, 256, 256, 0);
        add_ln_kernel<<<M, 256>>>(xin, tmp, ln1_g + i * 256, ln1_b + i * 256, xb);

        gemm_tc_kernel<<<dim3(8, GM), 256>>>(xb, W1 + (size_t)i * 256 * 1024,
                                             b1 + i * 1024, hid, M, 1024, 256, 1);
        gemm_tc_kernel<<<dim3(2, GM), 256>>>(hid, W2 + (size_t)i * 1024 * 256,
                                             b2 + i * 256, tmp, M, 256, 1024, 0);

        float* lnout = (i == NUM_LAYERS - 1) ? (float*)d_out : xb;
        add_ln_kernel<<<M, 256>>>(xb, tmp, ln2_g + i * 256, ln2_b + i * 256, lnout);
    }
}